// round 12
// baseline (speedup 1.0000x reference)
#include <cuda_runtime.h>

// RoiPooling: fmap [1,128,128,256] f32 NHWC, roi_edges [R,4] f32
// out [R,7,7,256] f32. Adaptive max pool, reference _bin_size semantics.
//
// R10 structure (mw-specialized batched loads, 2-way column split,
// predicated tail) + two out-rows per block: grid (R,4), p<3 -> rows
// {p, p+4}, p=3 -> row 3. Amortizes the ROI prologue ~1.75x, flattens
// per-block work (2mh / 2mh / mh+tail / mh), fewer blocks -> smaller
// launch tail, cross-row load overlap at row boundaries.

#define H_DIM 128
#define W_DIM 128
#define C_VEC 64          // 256 channels / 4 (float4)
#define OUT_H 7
#define OUT_W 7
#define ROW_STRIDE (W_DIM * C_VEC)    // float4 elems per fmap row (8192)

__device__ __forceinline__ int bin_size(int L) {
    int xup = (L + OUT_H - 1) / OUT_H;            // ceil(L/7)
    int m = (xup * (OUT_H - 1) >= L) ? (xup - 1) : xup;
    return m > 1 ? m : 1;
}

__device__ __forceinline__ void fold(float4& a, const float4 v) {
    a.x = fmaxf(a.x, v.x);
    a.y = fmaxf(a.y, v.y);
    a.z = fmaxf(a.z, v.z);
    a.w = fmaxf(a.w, v.w);
}

// Process one out-row for one half (ty=0: bins [0,JS); ty=1: bins [JS,7)
// incl. predicated tail). Batched loads (front-batched LDGs, MLP=NL).
template<int MW, bool FIRST>
__device__ __forceinline__ void run_row(const float4* __restrict__ fp,
                                        int cnt, int wl,
                                        float4* __restrict__ obase)
{
    constexpr int JS = (14 * MW + 7) / (4 * MW);   // MW=1..5 -> 5,4,4,3,3
    constexpr int J0 = FIRST ? 0 : JS;
    constexpr int J1 = FIRST ? JS : (OUT_W - 1);   // full-width bins only
    constexpr int NB = (FIRST ? JS : OUT_W - JS);  // accs incl. tail bin
    constexpr int NL = (J1 - J0) * MW;             // batched loads per row

    const float NEG = __int_as_float(0xff800000);   // -inf
    float4 acc[NB];
#pragma unroll
    for (int j = 0; j < NB; ++j)
        acc[j] = make_float4(NEG, NEG, NEG, NEG);

    int roff = 0;                                   // 32-bit row offset
#pragma unroll 2
    for (int y = 0; y < cnt; ++y) {
        const float4* row = fp + roff;
        roff += ROW_STRIDE;

        float4 v[NL];
#pragma unroll
        for (int u = 0; u < NL; ++u)
            v[u] = __ldg(row + (J0 * MW + u) * C_VEC);
#pragma unroll
        for (int u = 0; u < NL; ++u)
            fold(acc[u / MW], v[u]);

        if (!FIRST) {
            const float4* rowt = row + (OUT_W - 1) * MW * C_VEC;
#pragma unroll
            for (int k = 0; k < 6; ++k) {
                if (k < wl)
                    fold(acc[NB - 1], __ldg(rowt + k * C_VEC));
            }
        }
    }

#pragma unroll
    for (int j = 0; j < NB; ++j)
        obase[(J0 + j) * C_VEC] = acc[j];
}

template<int MW, bool FIRST>
__device__ __forceinline__ void run_block(const float4* __restrict__ fbase,
                                          int p, int mh, int Lh, int wl,
                                          float4* __restrict__ oroi)
{
    // Row 1: i = p (cnt = mh; for p=3 row 3 is never the tail row since
    // tail is row 6, and i*mh+mh <= Lh holds for i<6 by construction).
    {
        const int i = p;
        const float4* fp = fbase + (i * mh) * ROW_STRIDE;
        run_row<MW, FIRST>(fp, mh, wl, oroi + i * OUT_W * C_VEC);
    }
    // Row 2: i = p + 4 (p<3). Row 6 takes the tail count.
    if (p < 3) {
        const int i = p + 4;
        int cnt = (i == OUT_H - 1) ? (Lh - 6 * mh) : mh;
        const float4* fp = fbase + (i * mh) * ROW_STRIDE;
        run_row<MW, FIRST>(fp, cnt, wl, oroi + i * OUT_W * C_VEC);
    }
}

__global__ __launch_bounds__(128, 6)
void roi_pool_kernel(const float4* __restrict__ fmap,   // [128,128,64] float4
                     const float4* __restrict__ rois,   // [R] (l,r,t,b)
                     float4* __restrict__ out)          // [R,7,7,64] float4
{
    const int r   = blockIdx.x;       // ROI index
    const int p   = blockIdx.y;       // row-pair 0..3
    const int tid = threadIdx.x;      // 0..63 channel-group
    const bool first = (threadIdx.y == 0);

    const float4 e = rois[r];
    const int l  = __float2int_rn(128.0f * e.x);
    const int rr = __float2int_rn(128.0f * e.y);
    const int t  = __float2int_rn(128.0f * e.z);
    const int b  = __float2int_rn(128.0f * e.w);

    int Lh = b - t; Lh = Lh < OUT_H ? OUT_H : (Lh > 32 ? 32 : Lh);
    int Lw = rr - l; Lw = Lw < OUT_W ? OUT_W : (Lw > 32 ? 32 : Lw);

    const int mh = bin_size(Lh);
    const int mw = bin_size(Lw);
    const int wl = Lw - (OUT_W - 1) * mw;          // last-bin width, 1..6

    const float4* fbase = fmap + (t * W_DIM + l) * C_VEC + tid;
    float4* oroi = out + (r * OUT_H * OUT_W) * C_VEC + tid;

    switch (mw) {
        case 1:
            if (first) run_block<1, true >(fbase, p, mh, Lh, wl, oroi);
            else       run_block<1, false>(fbase, p, mh, Lh, wl, oroi);
            break;
        case 2:
            if (first) run_block<2, true >(fbase, p, mh, Lh, wl, oroi);
            else       run_block<2, false>(fbase, p, mh, Lh, wl, oroi);
            break;
        case 3:
            if (first) run_block<3, true >(fbase, p, mh, Lh, wl, oroi);
            else       run_block<3, false>(fbase, p, mh, Lh, wl, oroi);
            break;
        case 4:
            if (first) run_block<4, true >(fbase, p, mh, Lh, wl, oroi);
            else       run_block<4, false>(fbase, p, mh, Lh, wl, oroi);
            break;
        default:
            if (first) run_block<5, true >(fbase, p, mh, Lh, wl, oroi);
            else       run_block<5, false>(fbase, p, mh, Lh, wl, oroi);
            break;
    }
}

extern "C" void kernel_launch(void* const* d_in, const int* in_sizes, int n_in,
                              void* d_out, int out_size)
{
    const float4* fmap = (const float4*)d_in[0];   // [1,128,128,256] f32
    const float4* rois = (const float4*)d_in[1];   // [R,4] f32
    float4* out = (float4*)d_out;

    const int R = in_sizes[1] / 4;

    dim3 grid(R, 4);
    dim3 block(C_VEC, 2);
    roi_pool_kernel<<<grid, block>>>(fmap, rois, out);
}

// round 13
// speedup vs baseline: 1.0016x; 1.0016x over previous
#include <cuda_runtime.h>

// RoiPooling: fmap [1,128,128,256] f32 NHWC, roi_edges [R,4] f32
// out [R,7,7,256] f32. Adaptive max pool, reference _bin_size semantics.
//
// R10 structure (best: 18.8us): grid (R,7), mw-specialized batched loads,
// 2-way column split. This round: tail bin folded into the main batch via
// clamped indices (duplicate loads are L1 hits on a just-fetched line ->
// zero extra L2 traffic, no predication ALU, +6 batch MLP).

#define H_DIM 128
#define W_DIM 128
#define C_VEC 64          // 256 channels / 4 (float4)
#define OUT_H 7
#define OUT_W 7
#define ROW_STRIDE (W_DIM * C_VEC)    // float4 elems per fmap row (8192)

__device__ __forceinline__ int bin_size(int L) {
    int xup = (L + OUT_H - 1) / OUT_H;            // ceil(L/7)
    int m = (xup * (OUT_H - 1) >= L) ? (xup - 1) : xup;
    return m > 1 ? m : 1;
}

__device__ __forceinline__ void fold(float4& a, const float4 v) {
    a.x = fmaxf(a.x, v.x);
    a.y = fmaxf(a.y, v.y);
    a.z = fmaxf(a.z, v.z);
    a.w = fmaxf(a.w, v.w);
}

// One half-block: ty=0 handles bins [0,JS), ty=1 handles [JS,7) incl. the
// tail bin. Full-width bins load as one front-batched temp array per row.
// Tail bin (dynamic width wl in [1,6]) uses clamped indices so its 6 loads
// join the batch branch-free; duplicates hit L1 (no L2 cost, max idempotent).
template<int MW, bool FIRST>
__device__ __forceinline__ void run_half(const float4* __restrict__ fp,
                                         int cnt, int wl,
                                         float4* __restrict__ obase)
{
    constexpr int JS = (14 * MW + 7) / (4 * MW);   // MW=1..5 -> 5,4,4,3,3
    constexpr int J0 = FIRST ? 0 : JS;
    constexpr int J1 = FIRST ? JS : (OUT_W - 1);   // full-width bins
    constexpr int NB = (FIRST ? JS : OUT_W - JS);  // accs incl. tail bin
    constexpr int NL = (J1 - J0) * MW;             // full-width loads per row

    const float NEG = __int_as_float(0xff800000);   // -inf
    float4 acc[NB];
#pragma unroll
    for (int j = 0; j < NB; ++j)
        acc[j] = make_float4(NEG, NEG, NEG, NEG);

    // Clamped tail offsets (second half only): k -> min(k, wl-1).
    int toff[FIRST ? 1 : 6];
    if (!FIRST) {
        const int base = (OUT_W - 1) * MW * C_VEC;
#pragma unroll
        for (int k = 0; k < 6; ++k) {
            int kk = k < wl ? k : (wl - 1);
            toff[k] = base + kk * C_VEC;
        }
    }

    int roff = 0;                                   // 32-bit row offset
#pragma unroll 2
    for (int y = 0; y < cnt; ++y) {
        const float4* row = fp + roff;
        roff += ROW_STRIDE;

        // Front-batched loads: full-width bins + (second half) clamped tail.
        float4 v[NL];
#pragma unroll
        for (int u = 0; u < NL; ++u)
            v[u] = __ldg(row + (J0 * MW + u) * C_VEC);

        float4 tv[FIRST ? 1 : 6];
        if (!FIRST) {
#pragma unroll
            for (int k = 0; k < 6; ++k)
                tv[k] = __ldg(row + toff[k]);
        }

#pragma unroll
        for (int u = 0; u < NL; ++u)
            fold(acc[u / MW], v[u]);
        if (!FIRST) {
#pragma unroll
            for (int k = 0; k < 6; ++k)
                fold(acc[NB - 1], tv[k]);
        }
    }

#pragma unroll
    for (int j = 0; j < NB; ++j)
        obase[(J0 + j) * C_VEC] = acc[j];
}

__global__ __launch_bounds__(128, 6)
void roi_pool_kernel(const float4* __restrict__ fmap,   // [128,128,64] float4
                     const float4* __restrict__ rois,   // [R] (l,r,t,b)
                     float4* __restrict__ out)          // [R,7,7,64] float4
{
    const int r   = blockIdx.x;       // ROI index
    const int i   = blockIdx.y;       // output row 0..6
    const int tid = threadIdx.x;      // 0..63 channel-group
    const bool first = (threadIdx.y == 0);

    const float4 e = rois[r];
    const int l  = __float2int_rn(128.0f * e.x);
    const int rr = __float2int_rn(128.0f * e.y);
    const int t  = __float2int_rn(128.0f * e.z);
    const int b  = __float2int_rn(128.0f * e.w);

    int Lh = b - t; Lh = Lh < OUT_H ? OUT_H : (Lh > 32 ? 32 : Lh);
    int Lw = rr - l; Lw = Lw < OUT_W ? OUT_W : (Lw > 32 ? 32 : Lw);

    const int mh = bin_size(Lh);
    const int mw = bin_size(Lw);
    const int wl = Lw - (OUT_W - 1) * mw;          // last-bin width, 1..6

    const int y0 = i * mh;
    int y1 = (i == OUT_H - 1) ? Lh : (i + 1) * mh;
    if (y1 > Lh) y1 = Lh;
    const int cnt = y1 - y0;                       // 1..6

    const float4* fp = fmap + ((t + y0) * W_DIM + l) * C_VEC + tid;
    float4* obase = out + ((r * OUT_H + i) * OUT_W) * C_VEC + tid;

    switch (mw) {
        case 1:
            if (first) run_half<1, true >(fp, cnt, wl, obase);
            else       run_half<1, false>(fp, cnt, wl, obase);
            break;
        case 2:
            if (first) run_half<2, true >(fp, cnt, wl, obase);
            else       run_half<2, false>(fp, cnt, wl, obase);
            break;
        case 3:
            if (first) run_half<3, true >(fp, cnt, wl, obase);
            else       run_half<3, false>(fp, cnt, wl, obase);
            break;
        case 4:
            if (first) run_half<4, true >(fp, cnt, wl, obase);
            else       run_half<4, false>(fp, cnt, wl, obase);
            break;
        default:
            if (first) run_half<5, true >(fp, cnt, wl, obase);
            else       run_half<5, false>(fp, cnt, wl, obase);
            break;
    }
}

extern "C" void kernel_launch(void* const* d_in, const int* in_sizes, int n_in,
                              void* d_out, int out_size)
{
    const float4* fmap = (const float4*)d_in[0];   // [1,128,128,256] f32
    const float4* rois = (const float4*)d_in[1];   // [R,4] f32
    float4* out = (float4*)d_out;

    const int R = in_sizes[1] / 4;

    dim3 grid(R, OUT_H);
    dim3 block(C_VEC, 2);
    roi_pool_kernel<<<grid, block>>>(fmap, rois, out);
}

// round 14
// speedup vs baseline: 1.0190x; 1.0175x over previous
#include <cuda_runtime.h>

// RoiPooling: fmap [1,128,128,256] f32 NHWC, roi_edges [R,4] f32
// out [R,7,7,256] f32. Adaptive max pool, reference _bin_size semantics.
//
// Two kernels (both in one graph-captured launch):
//  1) build_ty1: Ty1[y] = max(fmap[y], fmap[y+1]) for y<127 (shared across
//     all ROIs). 16.8MB __device__ table.
//  2) gather (R10 structure, best known): per (roi,out-row) block, the
//     cnt-row bin is covered by <=3 overlapping 2-row windows from Ty1
//     (or 1 fmap row when cnt==1). Row reads drop to 0.596x -> total L2
//     traffic 221MB -> 177MB. We are LTS-capped, so dur ~ bytes.

#define W_DIM 128
#define C_VEC 64                     // 256 channels / 4 (float4)
#define OUT_H 7
#define OUT_W 7
#define ROWF4 (W_DIM * C_VEC)        // float4 elems per row (8192)

__device__ float4 g_ty1[128][ROWF4]; // row y = max(f[y], f[y+1]), y in [0,127)

__device__ __forceinline__ int bin_size(int L) {
    int xup = (L + OUT_H - 1) / OUT_H;            // ceil(L/7)
    int m = (xup * (OUT_H - 1) >= L) ? (xup - 1) : xup;
    return m > 1 ? m : 1;
}

__device__ __forceinline__ void fold(float4& a, const float4 v) {
    a.x = fmaxf(a.x, v.x);
    a.y = fmaxf(a.y, v.y);
    a.z = fmaxf(a.z, v.z);
    a.w = fmaxf(a.w, v.w);
}

// ---------------- build kernel ----------------
__global__ __launch_bounds__(256)
void build_ty1(const float4* __restrict__ fmap)
{
    const int col = blockIdx.x * 256 + threadIdx.x;   // 0..8191
    const int ys  = blockIdx.y * 8;                   // chunks of 8 rows
    const int ye  = (ys + 8 < 127) ? (ys + 8) : 127;

    float4 prev = __ldg(fmap + ys * ROWF4 + col);
#pragma unroll 4
    for (int y = ys; y < ye; ++y) {
        float4 cur = __ldg(fmap + (y + 1) * ROWF4 + col);
        float4 m;
        m.x = fmaxf(prev.x, cur.x);
        m.y = fmaxf(prev.y, cur.y);
        m.z = fmaxf(prev.z, cur.z);
        m.w = fmaxf(prev.w, cur.w);
        g_ty1[y][col] = m;
        prev = cur;
    }
}

// ---------------- gather kernel (R10 structure) ----------------
// One half-block: ty=0 bins [0,JS), ty=1 bins [JS,7) incl. predicated tail.
// base points at (t+y0)*ROWF4 + l*C_VEC + tid in either fmap (cnt==1) or
// g_ty1. Window rows: k<nr-1 -> 2k ; last -> lastoff.
template<int MW, bool FIRST>
__device__ __forceinline__ void run_half(const float4* __restrict__ base,
                                         int nr, int lastoff, int wl,
                                         float4* __restrict__ obase)
{
    constexpr int JS = (14 * MW + 7) / (4 * MW);   // MW=1..5 -> 5,4,4,3,3
    constexpr int J0 = FIRST ? 0 : JS;
    constexpr int J1 = FIRST ? JS : (OUT_W - 1);   // full-width bins only
    constexpr int NB = (FIRST ? JS : OUT_W - JS);  // accs incl. tail bin
    constexpr int NL = (J1 - J0) * MW;             // batched loads per row

    const float NEG = __int_as_float(0xff800000);   // -inf
    float4 acc[NB];
#pragma unroll
    for (int j = 0; j < NB; ++j)
        acc[j] = make_float4(NEG, NEG, NEG, NEG);

#pragma unroll 2
    for (int k = 0; k < nr; ++k) {
        const int yoff = (k == nr - 1) ? lastoff : 2 * k;
        const float4* row = base + yoff * ROWF4;

        // Front-batched independent loads for full-width bins.
        float4 v[NL];
#pragma unroll
        for (int u = 0; u < NL; ++u)
            v[u] = __ldg(row + (J0 * MW + u) * C_VEC);
#pragma unroll
        for (int u = 0; u < NL; ++u)
            fold(acc[u / MW], v[u]);

        if (!FIRST) {
            // Tail bin: dynamic width wl in [1,6], predicated.
            const float4* rowt = row + (OUT_W - 1) * MW * C_VEC;
#pragma unroll
            for (int kk = 0; kk < 6; ++kk) {
                if (kk < wl)
                    fold(acc[NB - 1], __ldg(rowt + kk * C_VEC));
            }
        }
    }

#pragma unroll
    for (int j = 0; j < NB; ++j)
        obase[(J0 + j) * C_VEC] = acc[j];
}

__global__ __launch_bounds__(128, 6)
void roi_pool_kernel(const float4* __restrict__ fmap,   // [128,128,64] float4
                     const float4* __restrict__ rois,   // [R] (l,r,t,b)
                     float4* __restrict__ out)          // [R,7,7,64] float4
{
    const int r   = blockIdx.x;       // ROI index
    const int i   = blockIdx.y;       // output row 0..6
    const int tid = threadIdx.x;      // 0..63 channel-group
    const bool first = (threadIdx.y == 0);

    const float4 e = rois[r];
    const int l  = __float2int_rn(128.0f * e.x);
    const int rr = __float2int_rn(128.0f * e.y);
    const int t  = __float2int_rn(128.0f * e.z);
    const int b  = __float2int_rn(128.0f * e.w);

    int Lh = b - t; Lh = Lh < OUT_H ? OUT_H : (Lh > 32 ? 32 : Lh);
    int Lw = rr - l; Lw = Lw < OUT_W ? OUT_W : (Lw > 32 ? 32 : Lw);

    const int mh = bin_size(Lh);
    const int mw = bin_size(Lw);
    const int wl = Lw - (OUT_W - 1) * mw;          // last-bin width, 1..6

    const int y0 = i * mh;
    int y1 = (i == OUT_H - 1) ? Lh : (i + 1) * mh;
    if (y1 > Lh) y1 = Lh;
    const int cnt = y1 - y0;                       // 1..6

    // 2-row-window cover of [y0, y0+cnt):
    //   cnt=1: fmap row y0
    //   cnt>=2: Ty1 rows {0,2,...} with last window at cnt-2 (overlap ok).
    const int nr      = (cnt + 1) >> 1;            // 1..3 rows to read
    const int lastoff = (cnt == 1) ? 0 : (cnt - 2);
    const int off     = ((t + y0) * W_DIM + l) * C_VEC + tid;
    const float4* base = (cnt == 1) ? (fmap + off) : (&g_ty1[0][0] + off);

    float4* obase = out + ((r * OUT_H + i) * OUT_W) * C_VEC + tid;

    switch (mw) {
        case 1:
            if (first) run_half<1, true >(base, nr, lastoff, wl, obase);
            else       run_half<1, false>(base, nr, lastoff, wl, obase);
            break;
        case 2:
            if (first) run_half<2, true >(base, nr, lastoff, wl, obase);
            else       run_half<2, false>(base, nr, lastoff, wl, obase);
            break;
        case 3:
            if (first) run_half<3, true >(base, nr, lastoff, wl, obase);
            else       run_half<3, false>(base, nr, lastoff, wl, obase);
            break;
        case 4:
            if (first) run_half<4, true >(base, nr, lastoff, wl, obase);
            else       run_half<4, false>(base, nr, lastoff, wl, obase);
            break;
        default:
            if (first) run_half<5, true >(base, nr, lastoff, wl, obase);
            else       run_half<5, false>(base, nr, lastoff, wl, obase);
            break;
    }
}

extern "C" void kernel_launch(void* const* d_in, const int* in_sizes, int n_in,
                              void* d_out, int out_size)
{
    const float4* fmap = (const float4*)d_in[0];   // [1,128,128,256] f32
    const float4* rois = (const float4*)d_in[1];   // [R,4] f32
    float4* out = (float4*)d_out;

    const int R = in_sizes[1] / 4;

    // Pass 1: build Ty1 (deterministic, graph-capturable).
    dim3 bgrid(ROWF4 / 256, 16);
    build_ty1<<<bgrid, 256>>>(fmap);

    // Pass 2: gather.
    dim3 grid(R, OUT_H);
    dim3 block(C_VEC, 2);
    roi_pool_kernel<<<grid, block>>>(fmap, rois, out);
}